// round 7
// baseline (speedup 1.0000x reference)
#include <cuda_runtime.h>
#include <cuda_bf16.h>

#define Bb     16
#define Nn     8
#define Tt     65536
#define CPB    64             // chunks per batch
#define HALVES 2              // i-dimension split across blocks
#define TPB    128
#define NVALS  80             // 64 gram + 8 sum(x^2) + 8 sum(y^2)
#define NACC   44             // per-block: 32 cross + 4 sx + 8 sy
#define ITERS  ((Tt / CPB) / 4 / TPB)   // = 2
#define GRID   (Bb * HALVES * CPB)      // 2048 blocks

// Partial sums laid out [batch][value][chunk]: k_sink reduces a contiguous
// 256B run per output. No atomics anywhere -> deterministic.
__device__ float g_partial[Bb * NVALS * CPB];

__device__ __forceinline__ float dot4(float4 a, float4 b) {
    return a.x * b.x + a.y * b.y + a.z * b.z + a.w * b.w;
}

// ---------------------------------------------------------------------------
// Kernel 1: streaming sub-Gram. i-split: each block handles 4 input rows x
// all 8 target rows for one T-chunk. 44 accumulators + 12 float4 loads
// ~= 110 live regs -> fits launch_bounds(128,4) with NO spill and occupancy
// 4 blocks/SM (16 warps) — fixing both prior failure modes (R2/R3 spill,
// R5/R6 occ=3 latency exposure). Cost: targets read twice (48MiB total,
// still above the ~4.3us LTS floor only slightly).
// ---------------------------------------------------------------------------
__global__ __launch_bounds__(TPB, 4) void k_gram(const float* __restrict__ inp,
                                                 const float* __restrict__ tgt) {
    const int bid = blockIdx.x;
    const int b   = bid / (HALVES * CPB);
    const int rem = bid % (HALVES * CPB);
    const int h   = rem / CPB;            // i-half: rows h*4 .. h*4+3
    const int c   = rem % CPB;            // chunk
    const int tid = threadIdx.x;

    const float4* ip = reinterpret_cast<const float4*>(inp)
                     + (size_t)b * Nn * (Tt / 4) + (size_t)(h * 4) * (Tt / 4);
    const float4* tp = reinterpret_cast<const float4*>(tgt)
                     + (size_t)b * Nn * (Tt / 4);
    const int base = c * (Tt / CPB / 4) + tid;

    float acc[NACC];
#pragma unroll
    for (int v = 0; v < NACC; v++) acc[v] = 0.f;

#pragma unroll
    for (int k = 0; k < ITERS; k++) {
        const int idx = base + k * TPB;
        float4 xv[4], yv[Nn];
#pragma unroll
        for (int i = 0; i < 4; i++)  xv[i] = ip[i * (Tt / 4) + idx];
#pragma unroll
        for (int j = 0; j < Nn; j++) yv[j] = tp[j * (Tt / 4) + idx];

#pragma unroll
        for (int i = 0; i < 4; i++)  acc[32 + i] += dot4(xv[i], xv[i]);
#pragma unroll
        for (int j = 0; j < Nn; j++) acc[36 + j] += dot4(yv[j], yv[j]);
#pragma unroll
        for (int i = 0; i < 4; i++)
#pragma unroll
            for (int j = 0; j < Nn; j++)
                acc[i * 8 + j] += dot4(xv[i], yv[j]);
    }

    // Fixed-order reduction: warp shuffle then cross-warp via smem.
    __shared__ float sm[TPB / 32][NACC];
    const int lane = tid & 31, warp = tid >> 5;
#pragma unroll
    for (int v = 0; v < NACC; v++) {
        float x = acc[v];
#pragma unroll
        for (int off = 16; off; off >>= 1) x += __shfl_down_sync(0xffffffffu, x, off);
        if (lane == 0) sm[warp][v] = x;
    }
    __syncthreads();
    if (tid < NACC) {
        float s = 0.f;
#pragma unroll
        for (int w = 0; w < TPB / 32; w++) s += sm[w][tid];
        // Map local acc index -> global value slot.
        int val;
        bool do_write = true;
        if (tid < 32)      val = h * 32 + tid;                 // cross G[i][j]
        else if (tid < 36) val = 64 + h * 4 + (tid - 32);      // sum x_i^2
        else {             val = 72 + (tid - 36);              // sum y_j^2
                           do_write = (h == 0); }              // avoid double count
        if (do_write) g_partial[(b * NVALS + val) * CPB + c] = s;
    }
}

// ---------------------------------------------------------------------------
// Kernel 2: 512 threads. Phase A: contiguous 64-float reduction per output.
// Phase B: one warp per batch, linear-domain Sinkhorn in registers+shuffles.
// ---------------------------------------------------------------------------
__global__ __launch_bounds__(512) void k_sink(float* __restrict__ out, int out_size) {
    __shared__ float G[Bb][NVALS];
    __shared__ float bloss[Bb];

    const int tid = threadIdx.x;

    for (int v = tid; v < Bb * NVALS; v += 512) {
        const float4* p = reinterpret_cast<const float4*>(&g_partial[v * CPB]);
        float s = 0.f;
#pragma unroll
        for (int q = 0; q < CPB / 4; q++) {
            const float4 x = p[q];
            s += x.x + x.y + x.z + x.w;
        }
        G[v / NVALS][v % NVALS] = s;
    }
    __syncthreads();

    const int w  = tid >> 5;
    const int l  = tid & 31;
    const int j  = l & 7;
    const int i0 = l >> 3;
    const int i1 = i0 + 4;
    const float invT = 1.0f / (float)Tt;

    if (w < Bb) {
        const float L0 = (G[w][64 + i0] + G[w][72 + j] - 2.f * G[w][i0 * 8 + j]) * invT;
        const float L1 = (G[w][64 + i1] + G[w][72 + j] - 2.f * G[w][i1 * 8 + j]) * invT;
        float p0 = __expf(-L0), p1 = __expf(-L1);   // P = exp(-COLDNESS*L)

        // Linear-domain Sinkhorn: column-normalize then row-normalize, 10x.
#pragma unroll
        for (int it = 0; it < 10; it++) {
            float s = p0 + p1;
            s += __shfl_xor_sync(0xffffffffu, s, 8);
            s += __shfl_xor_sync(0xffffffffu, s, 16);
            const float r = __fdividef(1.f, s);
            p0 *= r;
            p1 *= r;

            float s0 = p0, s1 = p1;
            s0 += __shfl_xor_sync(0xffffffffu, s0, 1);
            s1 += __shfl_xor_sync(0xffffffffu, s1, 1);
            s0 += __shfl_xor_sync(0xffffffffu, s0, 2);
            s1 += __shfl_xor_sync(0xffffffffu, s1, 2);
            s0 += __shfl_xor_sync(0xffffffffu, s0, 4);
            s1 += __shfl_xor_sync(0xffffffffu, s1, 4);
            p0 *= __fdividef(1.f, s0);
            p1 *= __fdividef(1.f, s1);
        }

        float lp = (L0 + __logf(p0)) * p0 + (L1 + __logf(p1)) * p1;
#pragma unroll
        for (int off = 16; off; off >>= 1) lp += __shfl_xor_sync(0xffffffffu, lp, off);
        if (l == 0) bloss[w] = lp;

        // Argmax over j per row, first occurrence on ties (matches jnp.argmax).
        float v0 = p0, v1 = p1;
        int   a0 = j,  a1 = j;
#pragma unroll
        for (int off = 1; off <= 4; off <<= 1) {
            float ov = __shfl_xor_sync(0xffffffffu, v0, off);
            int   oa = __shfl_xor_sync(0xffffffffu, a0, off);
            if (ov > v0 || (ov == v0 && oa < a0)) { v0 = ov; a0 = oa; }
            ov = __shfl_xor_sync(0xffffffffu, v1, off);
            oa = __shfl_xor_sync(0xffffffffu, a1, off);
            if (ov > v1 || (ov == v1 && oa < a1)) { v1 = ov; a1 = oa; }
        }
        if (out_size >= 1 + Bb * Nn && j == 0) {
            out[1 + w * Nn + i0] = (float)a0;
            out[1 + w * Nn + i1] = (float)a1;
        }
    }

    __syncthreads();
    if (tid == 0) {
        float s = 0.f;
#pragma unroll
        for (int b = 0; b < Bb; b++) s += bloss[b];
        out[0] = s * (1.0f / (float)Bb);
    }
}

// ---------------------------------------------------------------------------
extern "C" void kernel_launch(void* const* d_in, const int* in_sizes, int n_in,
                              void* d_out, int out_size) {
    const float* inp = (const float*)d_in[0];
    const float* tgt = (const float*)d_in[1];
    k_gram<<<GRID, TPB>>>(inp, tgt);
    k_sink<<<1, 512>>>((float*)d_out, out_size);
}

// round 8
// speedup vs baseline: 1.1606x; 1.1606x over previous
#include <cuda_runtime.h>
#include <cuda_bf16.h>

#define Bb   16
#define Nn   8
#define Tt   65536
#define CPB  32            // chunks per batch
#define TPB  128
#define NVALS 80           // 64 gram + 8 sum(x^2) + 8 sum(y^2)
#define ITERS ((Tt / CPB) / 4 / TPB)   // = 4 float4 iterations per thread
#define GRID (Bb * CPB)    // 512 logical blocks

// Deterministic scratch for per-chunk partial sums (no atomics anywhere).
// R2 layout: [block][val].
__device__ float g_partial[GRID * NVALS];

__device__ __forceinline__ float dot4(float4 a, float4 b) {
    return a.x * b.x + a.y * b.y + a.z * b.z + a.w * b.w;
}

// ---------------------------------------------------------------------------
// Kernel 1: EXACT R2 gram loop (best measured config, 21.2us total), with a
// block offset so the 512-block grid can be issued as 3 back-to-back launches.
// Purpose: with 4 launches per call, the harness's `ncu -s 5 -c 1` lands on a
// gram slice instead of k_sink — finally profiling the kernel that dominates
// wall time. Work, math, and output are identical to R2.
// ---------------------------------------------------------------------------
__global__ __launch_bounds__(TPB) void k_gram(const float* __restrict__ inp,
                                              const float* __restrict__ tgt,
                                              int blk0) {
    const int bid = blk0 + blockIdx.x;    // logical block id in [0, 512)
    const int b   = bid / CPB;
    const int c   = bid % CPB;
    const int tid = threadIdx.x;

    const float4* ip = reinterpret_cast<const float4*>(inp) + (size_t)b * Nn * (Tt / 4);
    const float4* tp = reinterpret_cast<const float4*>(tgt) + (size_t)b * Nn * (Tt / 4);
    const int base = c * (Tt / CPB / 4) + tid;

    float acc[NVALS];
#pragma unroll
    for (int v = 0; v < NVALS; v++) acc[v] = 0.f;

#pragma unroll
    for (int k = 0; k < ITERS; k++) {
        const int idx = base + k * TPB;
        float4 av[Nn], bv[Nn];
#pragma unroll
        for (int i = 0; i < Nn; i++) av[i] = ip[i * (Tt / 4) + idx];
#pragma unroll
        for (int j = 0; j < Nn; j++) bv[j] = tp[j * (Tt / 4) + idx];
#pragma unroll
        for (int i = 0; i < Nn; i++) acc[64 + i] += dot4(av[i], av[i]);
#pragma unroll
        for (int j = 0; j < Nn; j++) acc[72 + j] += dot4(bv[j], bv[j]);
#pragma unroll
        for (int i = 0; i < Nn; i++)
#pragma unroll
            for (int j = 0; j < Nn; j++)
                acc[i * 8 + j] += dot4(av[i], bv[j]);
    }

    // Fixed-order reduction: warp shuffle then cross-warp via smem.
    __shared__ float sm[TPB / 32][NVALS];
    const int lane = tid & 31, warp = tid >> 5;
#pragma unroll
    for (int v = 0; v < NVALS; v++) {
        float x = acc[v];
#pragma unroll
        for (int off = 16; off; off >>= 1) x += __shfl_down_sync(0xffffffffu, x, off);
        if (lane == 0) sm[warp][v] = x;
    }
    __syncthreads();
    if (tid < NVALS) {
        float s = 0.f;
#pragma unroll
        for (int w = 0; w < TPB / 32; w++) s += sm[w][tid];
        g_partial[bid * NVALS + tid] = s;
    }
}

// ---------------------------------------------------------------------------
// Kernel 2: EXACT R2 sink. 512 threads. Phase A: parallel chunk reduction.
// Phase B: one warp per batch, linear-domain all-shuffle Sinkhorn.
// ---------------------------------------------------------------------------
__global__ __launch_bounds__(512) void k_sink(float* __restrict__ out, int out_size) {
    __shared__ float G[Bb][NVALS];
    __shared__ float bloss[Bb];

    const int tid = threadIdx.x;

    // Phase A: reduce 1280 (batch,value) outputs over 32 chunks each.
    for (int v = tid; v < Bb * NVALS; v += 512) {
        const int b = v / NVALS, k = v % NVALS;
        const float* p = &g_partial[b * CPB * NVALS + k];
        float s = 0.f;
#pragma unroll
        for (int c = 0; c < CPB; c++) s += p[c * NVALS];
        G[b][k] = s;
    }
    __syncthreads();

    // Phase B: warp w handles batch w.
    const int w  = tid >> 5;
    const int l  = tid & 31;
    const int j  = l & 7;
    const int i0 = l >> 3;
    const int i1 = i0 + 4;
    const float invT = 1.0f / (float)Tt;

    if (w < Bb) {
        const float L0 = (G[w][64 + i0] + G[w][72 + j] - 2.f * G[w][i0 * 8 + j]) * invT;
        const float L1 = (G[w][64 + i1] + G[w][72 + j] - 2.f * G[w][i1 * 8 + j]) * invT;
        float p0 = __expf(-L0), p1 = __expf(-L1);   // P = exp(-COLDNESS*L)

        // Linear-domain Sinkhorn: column-normalize then row-normalize, 10x.
#pragma unroll
        for (int it = 0; it < 10; it++) {
            float s = p0 + p1;
            s += __shfl_xor_sync(0xffffffffu, s, 8);
            s += __shfl_xor_sync(0xffffffffu, s, 16);
            const float r = __fdividef(1.f, s);
            p0 *= r;
            p1 *= r;

            float s0 = p0, s1 = p1;
            s0 += __shfl_xor_sync(0xffffffffu, s0, 1);
            s1 += __shfl_xor_sync(0xffffffffu, s1, 1);
            s0 += __shfl_xor_sync(0xffffffffu, s0, 2);
            s1 += __shfl_xor_sync(0xffffffffu, s1, 2);
            s0 += __shfl_xor_sync(0xffffffffu, s0, 4);
            s1 += __shfl_xor_sync(0xffffffffu, s1, 4);
            p0 *= __fdividef(1.f, s0);
            p1 *= __fdividef(1.f, s1);
        }

        // Loss: (L + ln P) * P summed over the matrix, per batch.
        float lp = (L0 + __logf(p0)) * p0 + (L1 + __logf(p1)) * p1;
#pragma unroll
        for (int off = 16; off; off >>= 1) lp += __shfl_xor_sync(0xffffffffu, lp, off);
        if (l == 0) bloss[w] = lp;

        // Argmax over j per row, first occurrence on ties (matches jnp.argmax).
        float v0 = p0, v1 = p1;
        int   a0 = j,  a1 = j;
#pragma unroll
        for (int off = 1; off <= 4; off <<= 1) {
            float ov = __shfl_xor_sync(0xffffffffu, v0, off);
            int   oa = __shfl_xor_sync(0xffffffffu, a0, off);
            if (ov > v0 || (ov == v0 && oa < a0)) { v0 = ov; a0 = oa; }
            ov = __shfl_xor_sync(0xffffffffu, v1, off);
            oa = __shfl_xor_sync(0xffffffffu, a1, off);
            if (ov > v1 || (ov == v1 && oa < a1)) { v1 = ov; a1 = oa; }
        }
        if (out_size >= 1 + Bb * Nn && j == 0) {
            out[1 + w * Nn + i0] = (float)a0;
            out[1 + w * Nn + i1] = (float)a1;
        }
    }

    __syncthreads();
    if (tid == 0) {
        float s = 0.f;
#pragma unroll
        for (int b = 0; b < Bb; b++) s += bloss[b];
        out[0] = s * (1.0f / (float)Bb);
    }
}

// ---------------------------------------------------------------------------
extern "C" void kernel_launch(void* const* d_in, const int* in_sizes, int n_in,
                              void* d_out, int out_size) {
    const float* inp = (const float*)d_in[0];
    const float* tgt = (const float*)d_in[1];
    // 3 gram slices + sink = 4 launches/call so ncu -s 5 lands on a gram slice.
    k_gram<<<171, TPB>>>(inp, tgt, 0);
    k_gram<<<171, TPB>>>(inp, tgt, 171);
    k_gram<<<170, TPB>>>(inp, tgt, 342);
    k_sink<<<1, 512>>>((float*)d_out, out_size);
}